// round 6
// baseline (speedup 1.0000x reference)
#include <cuda_runtime.h>
#include <cuda_fp16.h>
#include <cstdint>

// ---------------- tiles ----------------
#define BM 256
#define BN 128
#define BK 64
#define STAGES 3
#define ROWB 144                                  // 64 halfs (128B) + 16B pad; conflict-free LDSM
#define A_STAGE_B (BM * ROWB)                     // 36864
#define B_STAGE_B (BN * ROWB)                     // 18432
#define STAGE_B   (A_STAGE_B + B_STAGE_B)         // 55296
#define SMEM_BYTES (STAGES * STAGE_B)             // 165888 (1 CTA/SM)

// ---------------- scratch (allocation-free rule) ----------------
__device__ __align__(1024) __half g_xt[33554432]; // x  -> fp16   [8192,4096]
__device__ __align__(1024) __half g_t [8388608];  // t = x @ V^T  [8192,1024]
__device__ __align__(1024) __half g_Us[4194304];  // (U cat)*s    [4096,1024]
__device__ __align__(1024) __half g_V [4194304];  // V cat        [1024,4096]

// ---------------- helpers ----------------
__device__ __forceinline__ void cp16(uint32_t s, const void* g) {
    asm volatile("cp.async.cg.shared.global [%0], [%1], 16;" :: "r"(s), "l"(g));
}
__device__ __forceinline__ void ldsm4(uint32_t* r, uint32_t addr) {
    asm volatile("ldmatrix.sync.aligned.m8n8.x4.shared.b16 {%0,%1,%2,%3}, [%4];"
                 : "=r"(r[0]), "=r"(r[1]), "=r"(r[2]), "=r"(r[3]) : "r"(addr));
}
__device__ __forceinline__ void mma16(float* c, const uint32_t* a, const uint32_t* b) {
    asm volatile("mma.sync.aligned.m16n8k16.row.col.f32.f16.f16.f32 "
                 "{%0,%1,%2,%3}, {%4,%5,%6,%7}, {%8,%9}, {%0,%1,%2,%3};"
                 : "+f"(c[0]), "+f"(c[1]), "+f"(c[2]), "+f"(c[3])
                 : "r"(a[0]), "r"(a[1]), "r"(a[2]), "r"(a[3]),
                   "r"(b[0]), "r"(b[1]));
}

// ---------------- pack: Us=(cat U)*s, V=cat V, x — all -> fp16 RN ----------------
#define US_F4 1048576
#define V_F4  1048576
#define X_F4  8388608
__global__ void pack_cvt(const float* __restrict__ x,
                         const float* __restrict__ u_t, const float* __restrict__ u_d,
                         const float* __restrict__ s,
                         const float* __restrict__ v_t, const float* __restrict__ v_d)
{
    int t = blockIdx.x * blockDim.x + threadIdx.x;
    if (t < US_F4) {
        int o = t >> 8, r4 = t & 255;
        float4 u = (r4 < 16) ? *(const float4*)(u_t + o * 64 + r4 * 4)
                             : *(const float4*)(u_d + o * 960 + r4 * 4 - 64);
        float4 sv = *(const float4*)(s + r4 * 4);
        __half2 h0 = __float22half2_rn(make_float2(u.x * sv.x, u.y * sv.y));
        __half2 h1 = __float22half2_rn(make_float2(u.z * sv.z, u.w * sv.w));
        *(uint2*)(g_Us + (size_t)t * 4) = make_uint2(*(uint32_t*)&h0, *(uint32_t*)&h1);
    } else if (t < US_F4 + V_F4) {
        int j = t - US_F4;
        int r = j >> 10;
        float4 v = (r < 64) ? *(const float4*)(v_t + (size_t)j * 4)
                            : *(const float4*)(v_d + (size_t)j * 4 - 64 * 4096);
        __half2 h0 = __float22half2_rn(make_float2(v.x, v.y));
        __half2 h1 = __float22half2_rn(make_float2(v.z, v.w));
        *(uint2*)(g_V + (size_t)j * 4) = make_uint2(*(uint32_t*)&h0, *(uint32_t*)&h1);
    } else {
        size_t i = (size_t)(t - US_F4 - V_F4) * 4;
        float4 v = *(const float4*)(x + i);
        __half2 h0 = __float22half2_rn(make_float2(v.x, v.y));
        __half2 h1 = __float22half2_rn(make_float2(v.z, v.w));
        *(uint2*)(g_xt + i) = make_uint2(*(uint32_t*)&h0, *(uint32_t*)&h1);
    }
}

// ---------------- fp16 mma GEMM: C[M,N] = A[M,K] @ B[N,K]^T (+bias) ----------------
// CTA tile 256x128, 8 warps (4 row-bands x 2 col-bands of 64x64).
template<bool HALF_OUT>
__global__ void __launch_bounds__(256, 1)
gemm_h(const __half* __restrict__ A, const __half* __restrict__ Bm,
       const float* __restrict__ bias, void* __restrict__ Cout,
       int N, int K)
{
    extern __shared__ __align__(16) char sm[];
    const uint32_t sbase = (uint32_t)__cvta_generic_to_shared(sm);
    const int tid  = threadIdx.x;
    const int lane = tid & 31;
    const int wid  = tid >> 5;
    const int wm   = wid >> 1;          // 0..3  row band (64)
    const int wn   = wid & 1;           // 0..1  col band (64)
    const int g    = lane >> 2;
    const int tg   = lane & 3;

    const int mBase = blockIdx.y * BM;
    const int nBase = blockIdx.x * BN;
    const __half* Ag = A  + (size_t)mBase * K;
    const __half* Bg = Bm + (size_t)nBase * K;

    // ldmatrix per-lane offsets within stage
    const int aRow = wm * 64 + (lane & 7) + ((lane >> 3) & 1) * 8;
    const int aKb  = (lane >> 4) * 16;
    const uint32_t aOff = (uint32_t)(aRow * ROWB + aKb);
    const int bRow = wn * 64 + (lane & 7) + (lane >> 4) * 8;
    const int bKb  = ((lane >> 3) & 1) * 16;
    const uint32_t bOff = (uint32_t)(bRow * ROWB + bKb) + A_STAGE_B;

    float c[4][8][4];
#pragma unroll
    for (int mt = 0; mt < 4; mt++)
#pragma unroll
        for (int nt = 0; nt < 8; nt++)
#pragma unroll
            for (int i = 0; i < 4; i++) c[mt][nt][i] = 0.f;

    // loads per stage: A 2048 chunks (8/thread), B 1024 chunks (4/thread), 16B each
    auto load_stage = [&](int st, int kt) {
        const uint32_t base = sbase + (uint32_t)st * STAGE_B;
        const size_t kOff = (size_t)kt * BK;
#pragma unroll
        for (int i = 0; i < 8; i++) {
            const int cid = i * 256 + tid;          // 0..2047
            const int row = cid >> 3;
            const uint32_t colB = (uint32_t)(cid & 7) * 16u;
            cp16(base + (uint32_t)(row * ROWB) + colB,
                 (const char*)(Ag + (size_t)row * K + kOff) + colB);
        }
#pragma unroll
        for (int i = 0; i < 4; i++) {
            const int cid = i * 256 + tid;          // 0..1023
            const int row = cid >> 3;
            const uint32_t colB = (uint32_t)(cid & 7) * 16u;
            cp16(base + A_STAGE_B + (uint32_t)(row * ROWB) + colB,
                 (const char*)(Bg + (size_t)row * K + kOff) + colB);
        }
        asm volatile("cp.async.commit_group;" ::: "memory");
    };

#pragma unroll
    for (int s = 0; s < STAGES - 1; s++) load_stage(s, s);

    const int KT = K / BK;
    for (int kt = 0; kt < KT; kt++) {
        asm volatile("cp.async.wait_group %0;" :: "n"(STAGES - 2) : "memory");
        __syncthreads();

        const int pf = kt + STAGES - 1;
        if (pf < KT) load_stage(pf % STAGES, pf);
        else asm volatile("cp.async.commit_group;" ::: "memory");

        const uint32_t stBase = sbase + (uint32_t)(kt % STAGES) * STAGE_B;

#pragma unroll
        for (int kk = 0; kk < BK / 16; kk++) {
            const uint32_t kByte = (uint32_t)(kk * 32);
            uint32_t a[4][4];
#pragma unroll
            for (int mt = 0; mt < 4; mt++)
                ldsm4(a[mt], stBase + aOff + (uint32_t)(mt * 16 * ROWB) + kByte);
#pragma unroll
            for (int np = 0; np < 4; np++) {
                uint32_t b[4];
                ldsm4(b, stBase + bOff + (uint32_t)(np * 16 * ROWB) + kByte);
#pragma unroll
                for (int mt = 0; mt < 4; mt++) {
                    mma16(c[mt][np * 2],     a[mt], b);
                    mma16(c[mt][np * 2 + 1], a[mt], b + 2);
                }
            }
        }
    }

    // ---- epilogue ----
#pragma unroll
    for (int mt = 0; mt < 4; mt++) {
        const int row = mBase + wm * 64 + mt * 16 + g;
#pragma unroll
        for (int nt = 0; nt < 8; nt++) {
            const int col = nBase + wn * 64 + nt * 8 + 2 * tg;
            if (HALF_OUT) {
                __half* C = (__half*)Cout;
                *(__half2*)(C + (size_t)row * N + col) =
                    __float22half2_rn(make_float2(c[mt][nt][0], c[mt][nt][1]));
                *(__half2*)(C + (size_t)(row + 8) * N + col) =
                    __float22half2_rn(make_float2(c[mt][nt][2], c[mt][nt][3]));
            } else {
                float* C = (float*)Cout;
                const float b0 = bias[col], b1 = bias[col + 1];
                *(float2*)(C + (size_t)row * N + col) =
                    make_float2(c[mt][nt][0] + b0, c[mt][nt][1] + b1);
                *(float2*)(C + (size_t)(row + 8) * N + col) =
                    make_float2(c[mt][nt][2] + b0, c[mt][nt][3] + b1);
            }
        }
    }
}

// ---------------- host ----------------
extern "C" void kernel_launch(void* const* d_in, const int* in_sizes, int n_in,
                              void* d_out, int out_size)
{
    const float* x    = (const float*)d_in[0];
    const float* u_t  = (const float*)d_in[1];
    const float* u_d  = (const float*)d_in[2];
    const float* s    = (const float*)d_in[3];
    const float* v_t  = (const float*)d_in[4];
    const float* v_d  = (const float*)d_in[5];
    const float* bias = (const float*)d_in[6];
    float* out = (float*)d_out;
    (void)in_sizes; (void)n_in; (void)out_size;

    __half *xt, *tbuf, *Us, *V;
    cudaGetSymbolAddress((void**)&xt,   g_xt);
    cudaGetSymbolAddress((void**)&tbuf, g_t);
    cudaGetSymbolAddress((void**)&Us,   g_Us);
    cudaGetSymbolAddress((void**)&V,    g_V);

    cudaFuncSetAttribute(gemm_h<true>,
                         cudaFuncAttributeMaxDynamicSharedMemorySize, SMEM_BYTES);
    cudaFuncSetAttribute(gemm_h<false>,
                         cudaFuncAttributeMaxDynamicSharedMemorySize, SMEM_BYTES);

    // 1) pack + fp16 conversion
    pack_cvt<<<(US_F4 + V_F4 + X_F4) / 256, 256>>>(x, u_t, u_d, s, v_t, v_d);

    // 2) t = x @ V^T     (M=8192, N=1024, K=4096), fp16 out
    gemm_h<true><<<dim3(1024 / BN, 8192 / BM), 256, SMEM_BYTES>>>(
        xt, V, nullptr, tbuf, 1024, 4096);

    // 3) out = t @ Us^T + bias  (M=8192, N=4096, K=1024), fp32 out
    gemm_h<false><<<dim3(4096 / BN, 8192 / BM), 256, SMEM_BYTES>>>(
        tbuf, Us, bias, out, 4096, 1024);
}

// round 7
// speedup vs baseline: 1.0595x; 1.0595x over previous
#include <cuda_runtime.h>
#include <cuda_fp16.h>
#include <cstdint>

// ---------------- tiles (R5 config: best so far) ----------------
#define BM 128
#define BN 128
#define BK 64
#define STAGES 3
#define ROWB 144                                  // 64 halfs (128B) + 16B pad; conflict-free LDSM
#define A_STAGE_B (BM * ROWB)                     // 18432
#define STAGE_B   (2 * A_STAGE_B)                 // 36864
#define SMEM_BYTES (STAGES * STAGE_B)             // 110592 (2 CTAs/SM)

// ---------------- scratch (allocation-free rule) ----------------
__device__ __align__(1024) __half g_xt[33554432]; // x  -> fp16   [8192,4096]
__device__ __align__(1024) __half g_t [8388608];  // t = x @ V^T  [8192,1024]
__device__ __align__(1024) __half g_Us[4194304];  // (U cat)*s    [4096,1024]
__device__ __align__(1024) __half g_V [4194304];  // V cat        [1024,4096]

// ---------------- helpers ----------------
__device__ __forceinline__ void cp16(uint32_t s, const void* g) {
    asm volatile("cp.async.cg.shared.global [%0], [%1], 16;" :: "r"(s), "l"(g));
}
__device__ __forceinline__ void ldsm4(uint32_t* r, uint32_t addr) {
    asm volatile("ldmatrix.sync.aligned.m8n8.x4.shared.b16 {%0,%1,%2,%3}, [%4];"
                 : "=r"(r[0]), "=r"(r[1]), "=r"(r[2]), "=r"(r[3]) : "r"(addr));
}
__device__ __forceinline__ void mma16(float* c, const uint32_t* a, const uint32_t* b) {
    asm volatile("mma.sync.aligned.m16n8k16.row.col.f32.f16.f16.f32 "
                 "{%0,%1,%2,%3}, {%4,%5,%6,%7}, {%8,%9}, {%0,%1,%2,%3};"
                 : "+f"(c[0]), "+f"(c[1]), "+f"(c[2]), "+f"(c[3])
                 : "r"(a[0]), "r"(a[1]), "r"(a[2]), "r"(a[3]),
                   "r"(b[0]), "r"(b[1]));
}

// ---------------- pack: Us=(cat U)*s, V=cat V, x — all -> fp16 RN ----------------
#define US_F4 1048576
#define V_F4  1048576
#define X_F4  8388608
__global__ void pack_cvt(const float* __restrict__ x,
                         const float* __restrict__ u_t, const float* __restrict__ u_d,
                         const float* __restrict__ s,
                         const float* __restrict__ v_t, const float* __restrict__ v_d)
{
    int t = blockIdx.x * blockDim.x + threadIdx.x;
    if (t < US_F4) {
        int o = t >> 8, r4 = t & 255;
        float4 u = (r4 < 16) ? *(const float4*)(u_t + o * 64 + r4 * 4)
                             : *(const float4*)(u_d + o * 960 + r4 * 4 - 64);
        float4 sv = *(const float4*)(s + r4 * 4);
        __half2 h0 = __float22half2_rn(make_float2(u.x * sv.x, u.y * sv.y));
        __half2 h1 = __float22half2_rn(make_float2(u.z * sv.z, u.w * sv.w));
        *(uint2*)(g_Us + (size_t)t * 4) = make_uint2(*(uint32_t*)&h0, *(uint32_t*)&h1);
    } else if (t < US_F4 + V_F4) {
        int j = t - US_F4;
        int r = j >> 10;
        float4 v = (r < 64) ? *(const float4*)(v_t + (size_t)j * 4)
                            : *(const float4*)(v_d + (size_t)j * 4 - 64 * 4096);
        __half2 h0 = __float22half2_rn(make_float2(v.x, v.y));
        __half2 h1 = __float22half2_rn(make_float2(v.z, v.w));
        *(uint2*)(g_V + (size_t)j * 4) = make_uint2(*(uint32_t*)&h0, *(uint32_t*)&h1);
    } else {
        size_t i = (size_t)(t - US_F4 - V_F4) * 4;
        float4 v = *(const float4*)(x + i);
        __half2 h0 = __float22half2_rn(make_float2(v.x, v.y));
        __half2 h1 = __float22half2_rn(make_float2(v.z, v.w));
        *(uint2*)(g_xt + i) = make_uint2(*(uint32_t*)&h0, *(uint32_t*)&h1);
    }
}

// ---------------- fp16 mma GEMM: C[M,N] = A[M,K] @ B[N,K]^T (+bias) ----------------
template<bool HALF_OUT>
__global__ void __launch_bounds__(128, 2)
gemm_h(const __half* __restrict__ A, const __half* __restrict__ Bm,
       const float* __restrict__ bias, void* __restrict__ Cout,
       int N, int K)
{
    extern __shared__ __align__(16) char sm[];
    const uint32_t sbase = (uint32_t)__cvta_generic_to_shared(sm);
    const int tid  = threadIdx.x;
    const int lane = tid & 31;
    const int wid  = tid >> 5;
    const int wm   = wid >> 1;          // 0..1 row band (64)
    const int wn   = wid & 1;           // 0..1 col band (64)
    const int g    = lane >> 2;
    const int tg   = lane & 3;

    const int mBase = blockIdx.y * BM;
    const int nBase = blockIdx.x * BN;
    const __half* Ag = A  + (size_t)mBase * K;
    const __half* Bg = Bm + (size_t)nBase * K;

    // ldmatrix per-lane offsets within stage
    const int aRow = wm * 64 + (lane & 7) + ((lane >> 3) & 1) * 8;
    const int aKb  = (lane >> 4) * 16;
    const uint32_t aOff = (uint32_t)(aRow * ROWB + aKb);
    const int bRow = wn * 64 + (lane & 7) + (lane >> 4) * 8;
    const int bKb  = ((lane >> 3) & 1) * 16;
    const uint32_t bOff = (uint32_t)(bRow * ROWB + bKb) + A_STAGE_B;

    float c[4][8][4];
#pragma unroll
    for (int mt = 0; mt < 4; mt++)
#pragma unroll
        for (int nt = 0; nt < 8; nt++)
#pragma unroll
            for (int i = 0; i < 4; i++) c[mt][nt][i] = 0.f;

    // loads: 8 A-chunks + 8 B-chunks of 16B per thread per stage, warp-coalesced
    auto load_stage = [&](int st, int kt) {
        const uint32_t base = sbase + (uint32_t)st * STAGE_B;
        const size_t kOff = (size_t)kt * BK;
#pragma unroll
        for (int i = 0; i < 8; i++) {
            const int cid = i * 128 + tid;          // 0..1023
            const int row = cid >> 3;
            const uint32_t colB = (uint32_t)(cid & 7) * 16u;
            cp16(base + (uint32_t)(row * ROWB) + colB,
                 (const char*)(Ag + (size_t)row * K + kOff) + colB);
            cp16(base + A_STAGE_B + (uint32_t)(row * ROWB) + colB,
                 (const char*)(Bg + (size_t)row * K + kOff) + colB);
        }
        asm volatile("cp.async.commit_group;" ::: "memory");
    };

#pragma unroll
    for (int s = 0; s < STAGES - 1; s++) load_stage(s, s);

    // fragment double buffers
    uint32_t a[2][4][4], b[2][4][4];

    const int KT = K / BK;
    for (int kt = 0; kt < KT; kt++) {
        asm volatile("cp.async.wait_group %0;" :: "n"(STAGES - 2) : "memory");
        __syncthreads();

        const int pf = kt + STAGES - 1;
        if (pf < KT) load_stage(pf % STAGES, pf);
        else asm volatile("cp.async.commit_group;" ::: "memory");

        const uint32_t stBase = sbase + (uint32_t)(kt % STAGES) * STAGE_B;

        // preload k16-step 0 fragments
#pragma unroll
        for (int mt = 0; mt < 4; mt++)
            ldsm4(a[0][mt], stBase + aOff + (uint32_t)(mt * 16 * ROWB));
#pragma unroll
        for (int np = 0; np < 4; np++)
            ldsm4(b[0][np], stBase + bOff + (uint32_t)(np * 16 * ROWB));

#pragma unroll
        for (int kk = 0; kk < BK / 16; kk++) {
            const int cur = kk & 1;
            const int nxt = cur ^ 1;
            if (kk < BK / 16 - 1) {                 // prefetch next k16 frags
                const uint32_t kByte = (uint32_t)((kk + 1) * 32);
#pragma unroll
                for (int mt = 0; mt < 4; mt++)
                    ldsm4(a[nxt][mt], stBase + aOff + (uint32_t)(mt * 16 * ROWB) + kByte);
#pragma unroll
                for (int np = 0; np < 4; np++)
                    ldsm4(b[nxt][np], stBase + bOff + (uint32_t)(np * 16 * ROWB) + kByte);
            }
#pragma unroll
            for (int np = 0; np < 4; np++)
#pragma unroll
                for (int mt = 0; mt < 4; mt++) {
                    mma16(c[mt][np * 2],     a[cur][mt], b[cur][np]);
                    mma16(c[mt][np * 2 + 1], a[cur][mt], b[cur][np] + 2);
                }
        }
    }

    // ---- epilogue ----
#pragma unroll
    for (int mt = 0; mt < 4; mt++) {
        const int row = mBase + wm * 64 + mt * 16 + g;
#pragma unroll
        for (int nt = 0; nt < 8; nt++) {
            const int col = nBase + wn * 64 + nt * 8 + 2 * tg;
            if (HALF_OUT) {
                __half* C = (__half*)Cout;
                *(__half2*)(C + (size_t)row * N + col) =
                    __float22half2_rn(make_float2(c[mt][nt][0], c[mt][nt][1]));
                *(__half2*)(C + (size_t)(row + 8) * N + col) =
                    __float22half2_rn(make_float2(c[mt][nt][2], c[mt][nt][3]));
            } else {
                float* C = (float*)Cout;
                const float b0 = bias[col], b1 = bias[col + 1];
                *(float2*)(C + (size_t)row * N + col) =
                    make_float2(c[mt][nt][0] + b0, c[mt][nt][1] + b1);
                *(float2*)(C + (size_t)(row + 8) * N + col) =
                    make_float2(c[mt][nt][2] + b0, c[mt][nt][3] + b1);
            }
        }
    }
}

// ---------------- host ----------------
extern "C" void kernel_launch(void* const* d_in, const int* in_sizes, int n_in,
                              void* d_out, int out_size)
{
    const float* x    = (const float*)d_in[0];
    const float* u_t  = (const float*)d_in[1];
    const float* u_d  = (const float*)d_in[2];
    const float* s    = (const float*)d_in[3];
    const float* v_t  = (const float*)d_in[4];
    const float* v_d  = (const float*)d_in[5];
    const float* bias = (const float*)d_in[6];
    float* out = (float*)d_out;
    (void)in_sizes; (void)n_in; (void)out_size;

    __half *xt, *tbuf, *Us, *V;
    cudaGetSymbolAddress((void**)&xt,   g_xt);
    cudaGetSymbolAddress((void**)&tbuf, g_t);
    cudaGetSymbolAddress((void**)&Us,   g_Us);
    cudaGetSymbolAddress((void**)&V,    g_V);

    cudaFuncSetAttribute(gemm_h<true>,
                         cudaFuncAttributeMaxDynamicSharedMemorySize, SMEM_BYTES);
    cudaFuncSetAttribute(gemm_h<false>,
                         cudaFuncAttributeMaxDynamicSharedMemorySize, SMEM_BYTES);

    // 1) pack + fp16 conversion
    pack_cvt<<<(US_F4 + V_F4 + X_F4) / 256, 256>>>(x, u_t, u_d, s, v_t, v_d);

    // 2) t = x @ V^T     (M=8192, N=1024, K=4096), fp16 out
    gemm_h<true><<<dim3(1024 / BN, 8192 / BM), 128, SMEM_BYTES>>>(
        xt, V, nullptr, tbuf, 1024, 4096);

    // 3) out = t @ Us^T + bias  (M=8192, N=4096, K=1024), fp32 out
    gemm_h<false><<<dim3(4096 / BN, 8192 / BM), 128, SMEM_BYTES>>>(
        tbuf, Us, bias, out, 4096, 1024);
}

// round 9
// speedup vs baseline: 1.0629x; 1.0032x over previous
#include <cuda_runtime.h>
#include <cuda_fp16.h>
#include <cstdint>

// ---------------- tiles ----------------
#define BM 128
#define BN 128
#define BK 64
#define STAGES 3
#define ROWB 144                                  // 64 halfs (128B) + 16B pad; conflict-free LDSM
#define A_STAGE_B (BM * ROWB)                     // 18432
#define STAGE_B   (2 * A_STAGE_B)                 // 36864
#define SMEM_BYTES (STAGES * STAGE_B)             // 110592 (2 CTAs/SM = 221KB)

// ---------------- scratch (allocation-free rule) ----------------
__device__ __align__(1024) __half g_xt[33554432]; // x  -> fp16   [8192,4096]
__device__ __align__(1024) __half g_t [8388608];  // t = x @ V^T  [8192,1024]
__device__ __align__(1024) __half g_Us[4194304];  // (U cat)*s    [4096,1024]
__device__ __align__(1024) __half g_V [4194304];  // V cat        [1024,4096]

// ---------------- helpers ----------------
__device__ __forceinline__ void cp16(uint32_t s, const void* g) {
    asm volatile("cp.async.cg.shared.global [%0], [%1], 16;" :: "r"(s), "l"(g));
}
__device__ __forceinline__ void ldsm4(uint32_t* r, uint32_t addr) {
    asm volatile("ldmatrix.sync.aligned.m8n8.x4.shared.b16 {%0,%1,%2,%3}, [%4];"
                 : "=r"(r[0]), "=r"(r[1]), "=r"(r[2]), "=r"(r[3]) : "r"(addr));
}
__device__ __forceinline__ void mma16(float* c, const uint32_t* a, const uint32_t* b) {
    asm volatile("mma.sync.aligned.m16n8k16.row.col.f32.f16.f16.f32 "
                 "{%0,%1,%2,%3}, {%4,%5,%6,%7}, {%8,%9}, {%0,%1,%2,%3};"
                 : "+f"(c[0]), "+f"(c[1]), "+f"(c[2]), "+f"(c[3])
                 : "r"(a[0]), "r"(a[1]), "r"(a[2]), "r"(a[3]),
                   "r"(b[0]), "r"(b[1]));
}

// ---------------- pack: Us=(cat U)*s, V=cat V, x — all -> fp16 RN ----------------
#define US_F4 1048576
#define V_F4  1048576
#define X_F4  8388608
__global__ void pack_cvt(const float* __restrict__ x,
                         const float* __restrict__ u_t, const float* __restrict__ u_d,
                         const float* __restrict__ s,
                         const float* __restrict__ v_t, const float* __restrict__ v_d)
{
    int t = blockIdx.x * blockDim.x + threadIdx.x;
    if (t < US_F4) {
        int o = t >> 8, r4 = t & 255;
        float4 u = (r4 < 16) ? *(const float4*)(u_t + o * 64 + r4 * 4)
                             : *(const float4*)(u_d + o * 960 + r4 * 4 - 64);
        float4 sv = *(const float4*)(s + r4 * 4);
        __half2 h0 = __float22half2_rn(make_float2(u.x * sv.x, u.y * sv.y));
        __half2 h1 = __float22half2_rn(make_float2(u.z * sv.z, u.w * sv.w));
        *(uint2*)(g_Us + (size_t)t * 4) = make_uint2(*(uint32_t*)&h0, *(uint32_t*)&h1);
    } else if (t < US_F4 + V_F4) {
        int j = t - US_F4;
        int r = j >> 10;
        float4 v = (r < 64) ? *(const float4*)(v_t + (size_t)j * 4)
                            : *(const float4*)(v_d + (size_t)j * 4 - 64 * 4096);
        __half2 h0 = __float22half2_rn(make_float2(v.x, v.y));
        __half2 h1 = __float22half2_rn(make_float2(v.z, v.w));
        *(uint2*)(g_V + (size_t)j * 4) = make_uint2(*(uint32_t*)&h0, *(uint32_t*)&h1);
    } else {
        size_t i = (size_t)(t - US_F4 - V_F4) * 4;
        float4 v = *(const float4*)(x + i);
        __half2 h0 = __float22half2_rn(make_float2(v.x, v.y));
        __half2 h1 = __float22half2_rn(make_float2(v.z, v.w));
        *(uint2*)(g_xt + i) = make_uint2(*(uint32_t*)&h0, *(uint32_t*)&h1);
    }
}

// ---------------- fp16 mma GEMM: C[M,N] = A[M,K] @ B[N,K]^T (+bias) ----------------
// 256 threads: 8 warps as 2 (row) x 4 (col); warp tile 64x32. 2 CTAs/SM -> 4 warps/SMSP.
template<bool HALF_OUT>
__global__ void __launch_bounds__(256, 2)
gemm_h(const __half* __restrict__ A, const __half* __restrict__ Bm,
       const float* __restrict__ bias, void* __restrict__ Cout,
       int N, int K)
{
    extern __shared__ __align__(16) char sm[];
    const uint32_t sbase = (uint32_t)__cvta_generic_to_shared(sm);
    const int tid  = threadIdx.x;
    const int lane = tid & 31;
    const int wid  = tid >> 5;
    const int wm   = wid >> 2;          // 0..1 row band (64)
    const int wn   = wid & 3;           // 0..3 col band (32)
    const int g    = lane >> 2;
    const int tg   = lane & 3;

    const int mBase = blockIdx.y * BM;
    const int nBase = blockIdx.x * BN;
    const __half* Ag = A  + (size_t)mBase * K;
    const __half* Bg = Bm + (size_t)nBase * K;

    // ldmatrix per-lane offsets within stage
    const int aRow = wm * 64 + (lane & 7) + ((lane >> 3) & 1) * 8;
    const int aKb  = (lane >> 4) * 16;
    const uint32_t aOff = (uint32_t)(aRow * ROWB + aKb);
    const int bRow = wn * 32 + (lane & 7) + (lane >> 4) * 8;
    const int bKb  = ((lane >> 3) & 1) * 16;
    const uint32_t bOff = (uint32_t)(bRow * ROWB + bKb) + A_STAGE_B;

    float c[4][4][4];
#pragma unroll
    for (int mt = 0; mt < 4; mt++)
#pragma unroll
        for (int nt = 0; nt < 4; nt++)
#pragma unroll
            for (int i = 0; i < 4; i++) c[mt][nt][i] = 0.f;

    // loads: 4 A-chunks + 4 B-chunks of 16B per thread per stage, warp-coalesced
    auto load_stage = [&](int st, int kt) {
        const uint32_t base = sbase + (uint32_t)st * STAGE_B;
        const size_t kOff = (size_t)kt * BK;
#pragma unroll
        for (int i = 0; i < 4; i++) {
            const int cid = i * 256 + tid;          // 0..1023
            const int row = cid >> 3;
            const uint32_t colB = (uint32_t)(cid & 7) * 16u;
            cp16(base + (uint32_t)(row * ROWB) + colB,
                 (const char*)(Ag + (size_t)row * K + kOff) + colB);
            cp16(base + A_STAGE_B + (uint32_t)(row * ROWB) + colB,
                 (const char*)(Bg + (size_t)row * K + kOff) + colB);
        }
        asm volatile("cp.async.commit_group;" ::: "memory");
    };

#pragma unroll
    for (int s = 0; s < STAGES - 1; s++) load_stage(s, s);

    const int KT = K / BK;
    for (int kt = 0; kt < KT; kt++) {
        asm volatile("cp.async.wait_group %0;" :: "n"(STAGES - 2) : "memory");
        __syncthreads();

        const int pf = kt + STAGES - 1;
        if (pf < KT) load_stage(pf % STAGES, pf);
        else asm volatile("cp.async.commit_group;" ::: "memory");

        const uint32_t stBase = sbase + (uint32_t)(kt % STAGES) * STAGE_B;

#pragma unroll
        for (int kk = 0; kk < BK / 16; kk++) {
            const uint32_t kByte = (uint32_t)(kk * 32);
            uint32_t a[4][4];
#pragma unroll
            for (int mt = 0; mt < 4; mt++)
                ldsm4(a[mt], stBase + aOff + (uint32_t)(mt * 16 * ROWB) + kByte);
#pragma unroll
            for (int np = 0; np < 2; np++) {
                uint32_t b[4];
                ldsm4(b, stBase + bOff + (uint32_t)(np * 16 * ROWB) + kByte);
#pragma unroll
                for (int mt = 0; mt < 4; mt++) {
                    mma16(c[mt][np * 2],     a[mt], b);
                    mma16(c[mt][np * 2 + 1], a[mt], b + 2);
                }
            }
        }
    }

    // ---- epilogue ----
#pragma unroll
    for (int mt = 0; mt < 4; mt++) {
        const int row = mBase + wm * 64 + mt * 16 + g;
#pragma unroll
        for (int nt = 0; nt < 4; nt++) {
            const int col = nBase + wn * 32 + nt * 8 + 2 * tg;
            if (HALF_OUT) {
                __half* C = (__half*)Cout;
                *(__half2*)(C + (size_t)row * N + col) =
                    __float22half2_rn(make_float2(c[mt][nt][0], c[mt][nt][1]));
                *(__half2*)(C + (size_t)(row + 8) * N + col) =
                    __float22half2_rn(make_float2(c[mt][nt][2], c[mt][nt][3]));
            } else {
                float* C = (float*)Cout;
                const float b0 = bias[col], b1 = bias[col + 1];
                *(float2*)(C + (size_t)row * N + col) =
                    make_float2(c[mt][nt][0] + b0, c[mt][nt][1] + b1);
                *(float2*)(C + (size_t)(row + 8) * N + col) =
                    make_float2(c[mt][nt][2] + b0, c[mt][nt][3] + b1);
            }
        }
    }
}

// ---------------- host ----------------
extern "C" void kernel_launch(void* const* d_in, const int* in_sizes, int n_in,
                              void* d_out, int out_size)
{
    const float* x    = (const float*)d_in[0];
    const float* u_t  = (const float*)d_in[1];
    const float* u_d  = (const float*)d_in[2];
    const float* s    = (const float*)d_in[3];
    const float* v_t  = (const float*)d_in[4];
    const float* v_d  = (const float*)d_in[5];
    const float* bias = (const float*)d_in[6];
    float* out = (float*)d_out;
    (void)in_sizes; (void)n_in; (void)out_size;

    __half *xt, *tbuf, *Us, *V;
    cudaGetSymbolAddress((void**)&xt,   g_xt);
    cudaGetSymbolAddress((void**)&tbuf, g_t);
    cudaGetSymbolAddress((void**)&Us,   g_Us);
    cudaGetSymbolAddress((void**)&V,    g_V);

    cudaFuncSetAttribute(gemm_h<true>,
                         cudaFuncAttributeMaxDynamicSharedMemorySize, SMEM_BYTES);
    cudaFuncSetAttribute(gemm_h<false>,
                         cudaFuncAttributeMaxDynamicSharedMemorySize, SMEM_BYTES);

    // 1) pack + fp16 conversion
    pack_cvt<<<(US_F4 + V_F4 + X_F4) / 256, 256>>>(x, u_t, u_d, s, v_t, v_d);

    // 2) t = x @ V^T     (M=8192, N=1024, K=4096), fp16 out
    gemm_h<true><<<dim3(1024 / BN, 8192 / BM), 256, SMEM_BYTES>>>(
        xt, V, nullptr, tbuf, 1024, 4096);

    // 3) out = t @ Us^T + bias  (M=8192, N=4096, K=1024), fp32 out
    gemm_h<false><<<dim3(4096 / BN, 8192 / BM), 256, SMEM_BYTES>>>(
        tbuf, Us, bias, out, 4096, 1024);
}